// round 14
// baseline (speedup 1.0000x reference)
#include <cuda_runtime.h>
#include <cstdint>

#define VOCAB 50257
#define DIM   2048
#define RNK   64
#define MT    64             // tokens per CTA
#define CCOLS 64             // d-columns per chunk
#define NCHUNK (DIM / CCOLS) // 32
#define NTHREADS 512
#define BSTRIDE 68           // bounce row stride (floats)

// B pre-transposed into per-(chunk64, ng, s, nt) fragment layout (512 KB)
__device__ float g_Bfrag[DIM * RNK];

__device__ __forceinline__ uint32_t smem_u32(const void* p) {
    uint32_t a;
    asm("{ .reg .u64 t; cvta.to.shared.u64 t, %1; cvt.u32.u64 %0, t; }" : "=r"(a) : "l"(p));
    return a;
}
__device__ __forceinline__ uint32_t to_tf32(float v) {
    uint32_t r;
    asm("cvt.rna.tf32.f32 %0, %1;" : "=r"(r) : "f"(v));
    return r;
}
__device__ __forceinline__ void cpa16(uint32_t dst, const void* src) {
    asm volatile("cp.async.cg.shared.global [%0], [%1], 16;" :: "r"(dst), "l"(src));
}
__device__ __forceinline__ void pf_l2(const void* p) {
    asm volatile("prefetch.global.L2 [%0];" :: "l"(p));
}
__device__ __forceinline__ void mma_tf32(float* d, const float4& a, const float2& b) {
    asm volatile(
        "mma.sync.aligned.m16n8k8.row.col.f32.tf32.tf32.f32 "
        "{%0,%1,%2,%3}, {%4,%5,%6,%7}, {%8,%9}, {%0,%1,%2,%3};"
        : "+f"(d[0]), "+f"(d[1]), "+f"(d[2]), "+f"(d[3])
        : "r"(__float_as_uint(a.x)), "r"(__float_as_uint(a.y)),
          "r"(__float_as_uint(a.z)), "r"(__float_as_uint(a.w)),
          "r"(__float_as_uint(b.x)), "r"(__float_as_uint(b.y)));
}
__device__ __forceinline__ void stcs2(float* p, float2 v) {
    asm volatile("st.global.cs.v2.f32 [%0], {%1, %2};" :: "l"(p), "f"(v.x), "f"(v.y));
}

// ---- prep: Bm[d][r] -> tf32 fragments grouped per (chunk64, ng, s, nt) ----
// float2 slot: (((c*4+ng)*8+s)*2+nt)*32 + lane ; lane = n8*4+(kq&3), reg = kq>>2
__global__ void prep_B(const float* __restrict__ Bm) {
    int idx = blockIdx.x * blockDim.x + threadIdx.x;   // 0..131071
    int d = idx >> 6, r = idx & 63;
    uint32_t tv = to_tf32(Bm[idx]);
    int c = d >> 6, colin = d & 63;
    int ng = colin >> 4, n16 = colin & 15;
    int nt = n16 >> 3, n8 = n16 & 7;
    int s = r >> 3, kq = r & 7;
    int lane = n8 * 4 + (kq & 3), reg = kq >> 2;
    int f2 = (((c * 4 + ng) * 8 + s) * 2 + nt) * 32 + lane;
    g_Bfrag[f2 * 2 + reg] = __uint_as_float(tv);
}

// ---- main: 512-thread CTA per 64-token tile (256 CTAs, 1 wave, 32 warps/SM) ----
__global__ void __launch_bounds__(NTHREADS, 2)
lora_main(const int* __restrict__ x,
          const float* __restrict__ W,
          const float* __restrict__ A,
          float* __restrict__ out) {
    extern __shared__ float sm[];
    float* As     = sm;                        // 4096 fl (16 KB): A fragments
    float* Bs     = sm + 4096;                 // 2 x 4096 fl (32 KB): B ping-pong
    float* bounce = sm + 4096 + 8192;          // 64*68 = 4352 fl (17 KB)
    int*   toks   = (int*)(sm + 4096 + 8192 + MT * BSTRIDE);

    const int tid   = threadIdx.x;
    const int tBase = blockIdx.x * MT;

    if (tid < MT) toks[tid] = x[tBase + tid];

    // prologue: prefetch B chunk 0 (16 KB)
    {
        uint32_t dst = smem_u32(Bs);
        #pragma unroll
        for (int j = 0; j < 2; ++j) {
            int i4 = j * NTHREADS + tid;
            cpa16(dst + i4 * 16, g_Bfrag + i4 * 4);
        }
        asm volatile("cp.async.commit_group;");
    }
    __syncthreads();   // toks visible

    // gather A into mma fragment layout (MT=64 mapping, validated R6-R11)
    #pragma unroll 2
    for (int i = tid; i < MT * RNK; i += NTHREADS) {
        int t = i & (MT - 1);
        int r = i >> 6;
        uint32_t tv = to_tf32(__ldg(A + (size_t)r * VOCAB + toks[t]));
        int s = r >> 3, kq = r & 7;
        int mtile = t >> 4, row16 = t & 15;
        int grp = row16 & 7, hi = row16 >> 3;
        int lane = grp * 4 + (kq & 3);
        int reg = (kq >> 2) * 2 + hi;
        As[((s * 4 + mtile) * 32 + lane) * 4 + reg] = __uint_as_float(tv);
    }

    const int wid  = tid >> 5;        // 0..15
    const int lane = tid & 31;
    const int mt   = wid >> 2;        // 0..3 : 16-token tile (MMA)
    const int ng   = wid & 3;         // 0..3 : 16-col group  (MMA)
    const int grp  = lane >> 2;
    const int tig  = lane & 3;

    // epilogue row ownership: warp owns rows {i*16 + wid}, i = 0..3
    int tokE[4];
    #pragma unroll
    for (int i = 0; i < 4; ++i) tokE[i] = toks[i * 16 + wid];

    // W L2 prefetch: lanes 0..7 cover 4 rows x 2 cache lines of the 256B/row slice
    const float* wPbase = nullptr;
    if (lane < 8) {
        int tokP = toks[(lane >> 1) * 16 + wid];
        wPbase = W + (size_t)tokP * DIM + (lane & 1) * 32;
        pf_l2(wPbase);   // chunk 0
    }

    #pragma unroll 1
    for (int c = 0; c < NCHUNK; ++c) {
        // prefetch B[c+1] into alternate buffer, then wait for B[c]
        if (c + 1 < NCHUNK) {
            const float* src = g_Bfrag + (c + 1) * 4096;
            uint32_t dst = smem_u32(Bs + ((c + 1) & 1) * 4096);
            #pragma unroll
            for (int j = 0; j < 2; ++j) {
                int i4 = j * NTHREADS + tid;
                cpa16(dst + i4 * 16, src + i4 * 4);
            }
            asm volatile("cp.async.commit_group;");
            asm volatile("cp.async.wait_group 1;");
        } else {
            asm volatile("cp.async.wait_group 0;");
        }
        __syncthreads();   // B[c] visible to all; bounce free (prev epilogue done)

        if (lane < 8 && c + 1 < NCHUNK) pf_l2(wPbase + (c + 1) * CCOLS);

        const float* curB = Bs + (c & 1) * 4096;

        // ---- MMA: warp tile m16 x n16, K=64 ----
        float acc[2][4];
        #pragma unroll
        for (int nt = 0; nt < 2; ++nt)
            #pragma unroll
            for (int k = 0; k < 4; ++k) acc[nt][k] = 0.f;

        #pragma unroll
        for (int s = 0; s < 8; ++s) {
            float4 a = *(const float4*)&As[((s * 4 + mt) * 32 + lane) * 4];
            #pragma unroll
            for (int nt = 0; nt < 2; ++nt) {
                float2 b = *(const float2*)&curB[(((ng * 8 + s) * 2 + nt) * 32 + lane) * 2];
                mma_tf32(acc[nt], a, b);
            }
        }

        // ---- STS acc -> bounce [row][col], stride 68 ----
        {
            int row0 = mt * 16 + grp;
            #pragma unroll
            for (int nt = 0; nt < 2; ++nt) {
                int col = ng * 16 + nt * 8 + tig * 2;
                *(float2*)&bounce[row0 * BSTRIDE + col] =
                    make_float2(acc[nt][0], acc[nt][1]);
                *(float2*)&bounce[(row0 + 8) * BSTRIDE + col] =
                    make_float2(acc[nt][2], acc[nt][3]);
            }
        }
        __syncthreads();   // bounce ready

        // ---- coalesced epilogue: 4 whole rows per warp; float2 accesses ----
        const int colB = c * CCOLS + lane * 2;
        float2 wv[4];
        #pragma unroll
        for (int i = 0; i < 4; ++i)
            wv[i] = __ldg((const float2*)(W + (size_t)tokE[i] * DIM + colB));
        #pragma unroll
        for (int i = 0; i < 4; ++i) {
            int row = i * 16 + wid;
            float2 l = *(const float2*)&bounce[row * BSTRIDE + lane * 2];
            float2 r;
            r.x = fmaf(16.f, l.x, wv[i].x);
            r.y = fmaf(16.f, l.y, wv[i].y);
            stcs2(out + (size_t)(tBase + row) * DIM + colB, r);
        }
    }
}

extern "C" void kernel_launch(void* const* d_in, const int* in_sizes, int n_in,
                              void* d_out, int out_size) {
    const int*   x  = (const int*)d_in[0];
    const float* W  = (const float*)d_in[1];
    const float* A  = (const float*)d_in[2];
    const float* Bm = (const float*)d_in[3];
    float* out = (float*)d_out;

    const int ntok = in_sizes[0];   // 16384

    const int smemBytes = (4096 + 8192 + MT * BSTRIDE) * 4 + MT * 4;   // 66,816 B
    cudaFuncSetAttribute(lora_main,
                         cudaFuncAttributeMaxDynamicSharedMemorySize, smemBytes);

    prep_B<<<(DIM * RNK) / 256, 256>>>(Bm);
    lora_main<<<ntok / MT, NTHREADS, smemBytes>>>(x, W, A, out);
}

// round 15
// speedup vs baseline: 1.3140x; 1.3140x over previous
#include <cuda_runtime.h>
#include <cstdint>

#define VOCAB 50257
#define DIM   2048
#define RNK   64
#define MT    64             // tokens per CTA
#define NDC   128            // d-columns per chunk
#define NCHUNK (DIM / NDC)   // 16
#define NTHREADS 256
#define BSTRIDE 132          // bounce row stride (floats)

// B pre-transposed into mma fragment layout, per 128-col chunk (512 KB)
__device__ float g_Bfrag[DIM * RNK];

__device__ __forceinline__ uint32_t smem_u32(const void* p) {
    uint32_t a;
    asm("{ .reg .u64 t; cvta.to.shared.u64 t, %1; cvt.u32.u64 %0, t; }" : "=r"(a) : "l"(p));
    return a;
}
__device__ __forceinline__ uint32_t to_tf32(float v) {
    uint32_t r;
    asm("cvt.rna.tf32.f32 %0, %1;" : "=r"(r) : "f"(v));
    return r;
}
__device__ __forceinline__ void cpa16(uint32_t dst, const void* src) {
    asm volatile("cp.async.cg.shared.global [%0], [%1], 16;" :: "r"(dst), "l"(src));
}
__device__ __forceinline__ void pf_l2(const void* p) {
    asm volatile("prefetch.global.L2 [%0];" :: "l"(p));
}
__device__ __forceinline__ void mma_tf32(float* d, const float4& a, const float2& b) {
    asm volatile(
        "mma.sync.aligned.m16n8k8.row.col.f32.tf32.tf32.f32 "
        "{%0,%1,%2,%3}, {%4,%5,%6,%7}, {%8,%9}, {%0,%1,%2,%3};"
        : "+f"(d[0]), "+f"(d[1]), "+f"(d[2]), "+f"(d[3])
        : "r"(__float_as_uint(a.x)), "r"(__float_as_uint(a.y)),
          "r"(__float_as_uint(a.z)), "r"(__float_as_uint(a.w)),
          "r"(__float_as_uint(b.x)), "r"(__float_as_uint(b.y)));
}
__device__ __forceinline__ void stcs4(float* p, float4 v) {
    asm volatile("st.global.cs.v4.f32 [%0], {%1, %2, %3, %4};"
                 :: "l"(p), "f"(v.x), "f"(v.y), "f"(v.z), "f"(v.w));
}

// ---- prep: Bm[d][r] (f32) -> tf32 fragment layout, per 128-d chunk ----
__global__ void prep_B(const float* __restrict__ Bm) {
    int idx = blockIdx.x * blockDim.x + threadIdx.x;   // 0..131071
    int d = idx >> 6, r = idx & 63;
    uint32_t tv = to_tf32(Bm[idx]);
    int chunk = d >> 7, n = d & 127;
    int s = r >> 3, kq = r & 7;
    int nt = n >> 3, n8 = n & 7;
    int lane = n8 * 4 + (kq & 3), reg = kq >> 2;
    g_Bfrag[chunk * 8192 + ((s * 16 + nt) * 32 + lane) * 2 + reg] = __uint_as_float(tv);
}

// ---- main: one CTA per 64-token tile (256 CTAs); A fragments register-resident ----
__global__ void __launch_bounds__(NTHREADS, 2)
lora_main(const int* __restrict__ x,
          const float* __restrict__ W,
          const float* __restrict__ A,
          float* __restrict__ out) {
    extern __shared__ float sm[];
    float* As     = sm;                    // 4096 floats (16 KB): A staging
    float* Bs     = sm + 4096;             // 8192 floats (32 KB, single buffer)
    float* bounce = sm + 4096 + 8192;      // 64*132 floats (33 KB)
    int*   toks   = (int*)(sm + 4096 + 8192 + MT * BSTRIDE);

    const int tid   = threadIdx.x;
    const int tBase = blockIdx.x * MT;

    if (tid < MT) toks[tid] = x[tBase + tid];

    // prologue: prefetch B chunk 0
    {
        uint32_t dst = smem_u32(Bs);
        #pragma unroll
        for (int j = 0; j < 8; ++j) {
            int i4 = j * NTHREADS + tid;
            cpa16(dst + i4 * 16, g_Bfrag + i4 * 4);
        }
        asm volatile("cp.async.commit_group;");
    }
    __syncthreads();   // toks visible

    // gather A into fragment layout (staging)
    #pragma unroll 4
    for (int i = tid; i < MT * RNK; i += NTHREADS) {
        int t = i & (MT - 1);
        int r = i >> 6;
        uint32_t tv = to_tf32(__ldg(A + (size_t)r * VOCAB + toks[t]));
        int s = r >> 3, kq = r & 7;
        int mtile = t >> 4, row16 = t & 15;
        int grp = row16 & 7, hi = row16 >> 3;
        int lane = grp * 4 + (kq & 3);
        int reg = (kq >> 2) * 2 + hi;
        As[((s * 4 + mtile) * 32 + lane) * 4 + reg] = __uint_as_float(tv);
    }
    __syncthreads();   // A staging complete

    const int wid  = tid >> 5;
    const int lane = tid & 31;
    const int mg   = wid >> 2;        // 0..1 : 32-token half  (MMA phase)
    const int ng   = wid & 3;         // 0..3 : 32-col quarter (MMA phase)
    const int grp  = lane >> 2;
    const int tig  = lane & 3;

    // ---- hoist this warp's A slice into registers ONCE (64 regs) ----
    float4 afrag[8][2];
    #pragma unroll
    for (int s = 0; s < 8; ++s)
        #pragma unroll
        for (int mt = 0; mt < 2; ++mt)
            afrag[s][mt] = *(const float4*)&As[((s * 4 + mg * 2 + mt) * 32 + lane) * 4];

    // epilogue row ownership: warp `wid` owns rows {i*8 + wid}, i=0..7
    int tokE[8];
    #pragma unroll
    for (int i = 0; i < 8; ++i) tokE[i] = toks[i * 8 + wid];

    // per-lane W L2-prefetch identity: row (lane>>2)*8+wid, 128B segment lane&3
    const int tokP = toks[(lane >> 2) * 8 + wid];
    const float* wPbase = W + (size_t)tokP * DIM + (lane & 3) * 32;
    pf_l2(wPbase);   // chunk 0's W slice

    #pragma unroll 1
    for (int c = 0; c < NCHUNK; ++c) {
        asm volatile("cp.async.wait_group 0;");
        __syncthreads();   // B[c] ready; bounce free (prev epilogue done)

        if (c + 1 < NCHUNK) pf_l2(wPbase + (c + 1) * NDC);

        // ---- MMA: warp tile m32 x n32, K=64; A from registers ----
        float acc[2][4][4];
        #pragma unroll
        for (int mt = 0; mt < 2; ++mt)
            #pragma unroll
            for (int nt = 0; nt < 4; ++nt)
                #pragma unroll
                for (int k = 0; k < 4; ++k) acc[mt][nt][k] = 0.f;

        #pragma unroll
        for (int s = 0; s < 8; ++s) {
            float2 b[4];
            #pragma unroll
            for (int nt = 0; nt < 4; ++nt)
                b[nt] = *(const float2*)&Bs[((s * 16 + ng * 4 + nt) * 32 + lane) * 2];
            #pragma unroll
            for (int mt = 0; mt < 2; ++mt)
                #pragma unroll
                for (int nt = 0; nt < 4; ++nt)
                    mma_tf32(acc[mt][nt], afrag[s][mt], b[nt]);
        }

        // ---- STS acc -> bounce [row][col], row stride 132 ----
        #pragma unroll
        for (int mt = 0; mt < 2; ++mt) {
            int row0 = mg * 32 + mt * 16 + grp;
            #pragma unroll
            for (int nt = 0; nt < 4; ++nt) {
                int col = ng * 32 + nt * 8 + tig * 2;
                *(float2*)&bounce[row0 * BSTRIDE + col] =
                    make_float2(acc[mt][nt][0], acc[mt][nt][1]);
                *(float2*)&bounce[(row0 + 8) * BSTRIDE + col] =
                    make_float2(acc[mt][nt][2], acc[mt][nt][3]);
            }
        }
        __syncthreads();   // bounce ready; Bs fully consumed

        // prefetch B[c+1] (overlaps epilogue's DRAM phase)
        if (c + 1 < NCHUNK) {
            const float* src = g_Bfrag + (c + 1) * 8192;
            uint32_t dst = smem_u32(Bs);
            #pragma unroll
            for (int j = 0; j < 8; ++j) {
                int i4 = j * NTHREADS + tid;
                cpa16(dst + i4 * 16, src + i4 * 4);
            }
            asm volatile("cp.async.commit_group;");
        }

        // ---- coalesced epilogue: 2 batches of 4 rows (caps reg pressure) ----
        const int colB = c * NDC + lane * 4;
        #pragma unroll
        for (int h = 0; h < 2; ++h) {
            float4 wv[4];
            #pragma unroll
            for (int i = 0; i < 4; ++i)
                wv[i] = __ldg((const float4*)(W + (size_t)tokE[h * 4 + i] * DIM + colB));
            #pragma unroll
            for (int i = 0; i < 4; ++i) {
                int row = (h * 4 + i) * 8 + wid;
                float4 l = *(const float4*)&bounce[row * BSTRIDE + lane * 4];
                float4 r;
                r.x = fmaf(16.f, l.x, wv[i].x);
                r.y = fmaf(16.f, l.y, wv[i].y);
                r.z = fmaf(16.f, l.z, wv[i].z);
                r.w = fmaf(16.f, l.w, wv[i].w);
                stcs4(out + (size_t)(tBase + row) * DIM + colB, r);
            }
        }
    }
}

extern "C" void kernel_launch(void* const* d_in, const int* in_sizes, int n_in,
                              void* d_out, int out_size) {
    const int*   x  = (const int*)d_in[0];
    const float* W  = (const float*)d_in[1];
    const float* A  = (const float*)d_in[2];
    const float* Bm = (const float*)d_in[3];
    float* out = (float*)d_out;

    const int ntok = in_sizes[0];   // 16384

    const int smemBytes = (4096 + 8192 + MT * BSTRIDE) * 4 + MT * 4;   // 83,200 B
    cudaFuncSetAttribute(lora_main,
                         cudaFuncAttributeMaxDynamicSharedMemorySize, smemBytes);

    prep_B<<<(DIM * RNK) / 256, 256>>>(Bm);
    lora_main<<<ntok / MT, NTHREADS, smemBytes>>>(x, W, A, out);
}